// round 10
// baseline (speedup 1.0000x reference)
#include <cuda_runtime.h>
#include <cstdint>

// Problem constants
#define B_ROWS 8192
#define D_DIM  1024
#define G_REP  8
#define N_TOT  (B_ROWS * D_DIM)          // 8,388,608 elements of xf
#define OUT_ROW (G_REP * D_DIM)          // 8192 floats per output row
#define EPS 1e-12f

#define SUM_BLOCKS 1184                  // 148 SMs * 8 -> single wave

// Scratch (no allocations allowed -> __device__ globals)
__device__ double       g_part[SUM_BLOCKS];
__device__ float        g_mean;
__device__ unsigned int g_count;         // zero-init; last block resets -> replay-safe

// ---------------------------------------------------------------------------
// Kernel 1: global sum of xf. Per-block partial (double), last-block ticket
// reduces partials -> g_mean, then resets the ticket counter (replay-safe).
// Side effect: streams all of xf through L2 (32 MB, fits 126 MB) so k_main's
// reads are L2 hits.
// ---------------------------------------------------------------------------
__global__ __launch_bounds__(256) void k_sum(const float* __restrict__ xf) {
    const int n4 = N_TOT / 4;
    const float4* __restrict__ x4 = reinterpret_cast<const float4*>(xf);

    double local = 0.0;
    int idx    = blockIdx.x * blockDim.x + threadIdx.x;
    int stride = gridDim.x * blockDim.x;
    for (int i = idx; i < n4; i += stride) {
        float4 v = __ldg(&x4[i]);
        local += (double)((v.x + v.y) + (v.z + v.w));
    }

    #pragma unroll
    for (int o = 16; o > 0; o >>= 1)
        local += __shfl_down_sync(0xffffffffu, local, o);

    __shared__ double smem[8];
    __shared__ bool   s_last;
    int lane = threadIdx.x & 31;
    int warp = threadIdx.x >> 5;
    if (lane == 0) smem[warp] = local;
    if (threadIdx.x == 0) s_last = false;
    __syncthreads();

    if (threadIdx.x == 0) {
        double blk = smem[0] + smem[1] + smem[2] + smem[3]
                   + smem[4] + smem[5] + smem[6] + smem[7];
        g_part[blockIdx.x] = blk;
        __threadfence();                              // partial visible before ticket
        unsigned int t = atomicAdd(&g_count, 1u);
        s_last = (t == (unsigned)(gridDim.x - 1));
    }
    __syncthreads();

    if (s_last) {
        double s = 0.0;
        for (int i = threadIdx.x; i < SUM_BLOCKS; i += 256)
            s += g_part[i];
        #pragma unroll
        for (int o = 16; o > 0; o >>= 1)
            s += __shfl_down_sync(0xffffffffu, s, o);
        if (lane == 0) smem[warp] = s;
        __syncthreads();
        if (threadIdx.x == 0) {
            double tot = smem[0] + smem[1] + smem[2] + smem[3]
                       + smem[4] + smem[5] + smem[6] + smem[7];
            g_mean  = (float)(tot * (1.0 / (double)N_TOT));
            g_count = 0;                              // replay-safe reset
        }
    }
}

// ---------------------------------------------------------------------------
// Kernel 2: warp-per-row, TWO-PASS over L1 instead of a register cache.
//   Pass 1: load the row's 8 float4s, accumulate relu'd sum-of-squares,
//           DISCARD values (no 32-reg v[8] cache -> regs <= 32).
//   Reduce: 5x shfl_xor butterfly, no smem, no __syncthreads.
//   Pass 2: reload each float4 (L1 hit; worst case L2 hit, ~32 MB total vs
//           the 256 MB store stream), apply relu+scale, 8 tiled __stcs.
// __launch_bounds__(256, 8): forces <=32 regs -> 8 blocks/SM -> capacity
// 1184 blocks >= 1024 grid -> SINGLE WAVE (R7 ran 1.38 waves at 5 blocks/SM,
// which is what held DRAM to 63.6%).
// ---------------------------------------------------------------------------
__global__ __launch_bounds__(256, 8) void k_main(const float* __restrict__ xf,
                                                 const float* __restrict__ wp,
                                                 float* __restrict__ out) {
    const float mean = g_mean;
    const int lane = threadIdx.x & 31;
    const int warp = threadIdx.x >> 5;
    const int row  = blockIdx.x * 8 + warp;

    const float4* __restrict__ xr =
        reinterpret_cast<const float4*>(xf + (size_t)row * D_DIM);

    // Pass 1: sum of squares of relu(x - mean), values discarded.
    float ss = 0.0f;
    #pragma unroll
    for (int i = 0; i < 8; i++) {
        float4 v = xr[i * 32 + lane];
        float a = fmaxf(v.x - mean, 0.0f);
        float b = fmaxf(v.y - mean, 0.0f);
        float c = fmaxf(v.z - mean, 0.0f);
        float d = fmaxf(v.w - mean, 0.0f);
        ss += a * a + b * b + c * c + d * d;
    }

    // Butterfly reduce: every lane ends with the row total.
    #pragma unroll
    for (int o = 16; o > 0; o >>= 1)
        ss += __shfl_xor_sync(0xffffffffu, ss, o);

    const float norm  = fmaxf(sqrtf(ss), EPS);
    const float sig   = 1.0f / (1.0f + __expf(-wp[0]));
    const float scale = sig / norm;

    // Pass 2: reload (L1-resident), transform, 8 tiled streaming stores.
    float4* __restrict__ orow =
        reinterpret_cast<float4*>(out + (size_t)row * OUT_ROW);
    #pragma unroll
    for (int i = 0; i < 8; i++) {
        float4 v = xr[i * 32 + lane];
        float4 o;
        o.x = fmaxf(v.x - mean, 0.0f) * scale;
        o.y = fmaxf(v.y - mean, 0.0f) * scale;
        o.z = fmaxf(v.z - mean, 0.0f) * scale;
        o.w = fmaxf(v.w - mean, 0.0f) * scale;
        #pragma unroll
        for (int g = 0; g < G_REP; g++) {
            __stcs(&orow[g * 256 + i * 32 + lane], o);
        }
    }
}

// ---------------------------------------------------------------------------
extern "C" void kernel_launch(void* const* d_in, const int* in_sizes, int n_in,
                              void* d_out, int out_size) {
    const float* xf = (const float*)d_in[0];
    const float* wp = (const float*)d_in[1];
    // d_in[2] is W_tile == kron(ones(1,8), eye(D)): the matmul is a pure 8x
    // tiling of fn_xf, so W_tile is never read.
    float* out = (float*)d_out;

    k_sum<<<SUM_BLOCKS, 256>>>(xf);
    k_main<<<B_ROWS / 8, 256>>>(xf, wp, out);
}

// round 11
// speedup vs baseline: 1.1170x; 1.1170x over previous
#include <cuda_runtime.h>
#include <cstdint>

// Problem constants
#define B_ROWS 8192
#define D_DIM  1024
#define G_REP  8
#define N_TOT  (B_ROWS * D_DIM)          // 8,388,608 elements of xf
#define OUT_ROW (G_REP * D_DIM)          // 8192 floats per output row
#define EPS 1e-12f
#define GRID (B_ROWS / 8)                // 1024 blocks, 8 rows (warps) each

// Scratch (no allocations allowed -> __device__ globals, zero-initialized)
__device__ double       g_sum;
__device__ unsigned int g_arrive;
__device__ unsigned int g_exit;
__device__ unsigned int g_release;

// ---------------------------------------------------------------------------
// Single fused kernel.
//   Phase 1 : each warp sums its OWN row (warms L1/L2 with exactly the data
//             it will transform later); block partial -> atomicAdd(double).
//   Barrier : software grid barrier (arrive counter + volatile release flag).
//             Safe because launch_bounds(256,8) guarantees 1184 co-resident
//             blocks >= grid 1024 (160-block cushion). Exit counter makes the
//             last block reset ALL state -> graph-replay deterministic.
//   Phase 2a: relu'd sum-of-squares over L1-warm reloads, shfl_xor butterfly.
//   Phase 2b: depth-1 pipelined reload -> relu+scale -> 8 tiled __stcs.
// Store phase is at the HBM write ceiling (~5 TB/s); this kernel removes the
// ~13us of k_sum-tail + launch-gap overhead the 2-kernel split paid.
// ---------------------------------------------------------------------------
__global__ __launch_bounds__(256, 8) void k_fused(const float* __restrict__ xf,
                                                  const float* __restrict__ wp,
                                                  float* __restrict__ out) {
    const int lane = threadIdx.x & 31;
    const int warp = threadIdx.x >> 5;
    const int row  = blockIdx.x * 8 + warp;

    const float4* __restrict__ xr =
        reinterpret_cast<const float4*>(xf + (size_t)row * D_DIM);

    __shared__ double s_warp[8];
    __shared__ float  s_mean;
    __shared__ float  s_sig;

    // ---- Phase 1: plain row sum (fp32 per lane over 32 elems, then double).
    float s = 0.0f;
    #pragma unroll
    for (int i = 0; i < 8; i++) {
        float4 v = xr[i * 32 + lane];
        s += (v.x + v.y) + (v.z + v.w);
    }
    double d = (double)s;
    #pragma unroll
    for (int o = 16; o > 0; o >>= 1)
        d += __shfl_down_sync(0xffffffffu, d, o);
    if (lane == 0) s_warp[warp] = d;
    __syncthreads();

    // ---- Grid barrier + mean computation (thread 0 only; others park at bar)
    if (threadIdx.x == 0) {
        double blk = s_warp[0] + s_warp[1] + s_warp[2] + s_warp[3]
                   + s_warp[4] + s_warp[5] + s_warp[6] + s_warp[7];
        atomicAdd(&g_sum, blk);
        __threadfence();                      // publish partial before arriving
        unsigned a = atomicAdd(&g_arrive, 1u);
        if (a == (unsigned)(GRID - 1)) {
            __threadfence();
            *(volatile unsigned int*)&g_release = 1u;
        } else {
            while (*(volatile unsigned int*)&g_release == 0u)
                __nanosleep(64);
        }
        __threadfence();                      // acquire: see all g_sum updates
        double tot = atomicAdd(&g_sum, 0.0);  // coherent read
        s_mean = (float)(tot * (1.0 / (double)N_TOT));
        s_sig  = 1.0f / (1.0f + __expf(-wp[0]));
    }
    __syncthreads();

    const float mean = s_mean;

    // ---- Phase 2a: relu'd sum of squares (reloads hit warm L1/L2;
    //      L1 persists within a launch, unlike the 2-kernel split).
    float ss = 0.0f;
    #pragma unroll
    for (int i = 0; i < 8; i++) {
        float4 v = xr[i * 32 + lane];
        float a = fmaxf(v.x - mean, 0.0f);
        float b = fmaxf(v.y - mean, 0.0f);
        float c = fmaxf(v.z - mean, 0.0f);
        float e = fmaxf(v.w - mean, 0.0f);
        ss += a * a + b * b + c * c + e * e;
    }
    #pragma unroll
    for (int o = 16; o > 0; o >>= 1)
        ss += __shfl_xor_sync(0xffffffffu, ss, o);

    const float scale = s_sig / fmaxf(sqrtf(ss), EPS);

    // ---- Phase 2b: pipelined reload, transform, 8 tiled streaming stores.
    float4* __restrict__ orow =
        reinterpret_cast<float4*>(out + (size_t)row * OUT_ROW);
    float4 v = xr[lane];
    #pragma unroll
    for (int i = 0; i < 8; i++) {
        float4 vn = (i < 7) ? xr[(i + 1) * 32 + lane] : v;   // prefetch next
        float4 o;
        o.x = fmaxf(v.x - mean, 0.0f) * scale;
        o.y = fmaxf(v.y - mean, 0.0f) * scale;
        o.z = fmaxf(v.z - mean, 0.0f) * scale;
        o.w = fmaxf(v.w - mean, 0.0f) * scale;
        #pragma unroll
        for (int g = 0; g < G_REP; g++)
            __stcs(&orow[g * 256 + i * 32 + lane], o);
        v = vn;
    }

    // ---- Exit: last block to leave resets barrier state (replay-safe).
    //      Exit count only completes after every block passed the spin, so
    //      no block can still be reading g_sum / g_release when we reset.
    __syncthreads();
    if (threadIdx.x == 0) {
        unsigned e = atomicAdd(&g_exit, 1u);
        if (e == (unsigned)(GRID - 1)) {
            g_sum    = 0.0;
            g_arrive = 0u;
            g_exit   = 0u;
            __threadfence();
            *(volatile unsigned int*)&g_release = 0u;
        }
    }
}

// ---------------------------------------------------------------------------
extern "C" void kernel_launch(void* const* d_in, const int* in_sizes, int n_in,
                              void* d_out, int out_size) {
    const float* xf = (const float*)d_in[0];
    const float* wp = (const float*)d_in[1];
    // d_in[2] is W_tile == kron(ones(1,8), eye(D)): the matmul is a pure 8x
    // tiling of fn_xf, so W_tile is never read.
    float* out = (float*)d_out;

    k_fused<<<GRID, 256>>>(xf, wp, out);
}